// round 9
// baseline (speedup 1.0000x reference)
#include <cuda_runtime.h>
#include <cuda_bf16.h>
#include <cstdint>

#define B__   256
#define NTOK  196
#define CDIM  256
#define NH    8
#define HDIM  32
#define MROWS (B__ * NTOK)          // 50176 = 392*128
#define KEXT  768                   // 3*256 split-bf16 K
#define QSCALE 0.17677669529663687f // 1/sqrt(32)

typedef unsigned long long ull;

// ---------------- scratch (device globals) ----------------
__device__ float g_q[MROWS * CDIM];
__device__ float g_k[MROWS * CDIM];
__device__ float g_v[MROWS * CDIM];
__device__ float g_o[MROWS * CDIM];
__device__ __nv_bfloat16 g_xb[(size_t)MROWS * KEXT]; // x split  [Ah, Al, Ah]
__device__ __nv_bfloat16 g_ob[(size_t)MROWS * KEXT]; // attn-out split
__device__ __nv_bfloat16 g_wq[768 * KEXT];           // qkv_w split [Bh, Bh, Bl]
__device__ __nv_bfloat16 g_wp[256 * KEXT];           // proj_w split

// ---------------- small PTX helpers ----------------
__device__ __forceinline__ uint32_t s2u(const void* p) {
    return (uint32_t)__cvta_generic_to_shared(p);
}
#define CP16(dst, src) \
    asm volatile("cp.async.ca.shared.global [%0], [%1], 16;" :: "r"(dst), "l"(src))
#define CP_COMMIT() asm volatile("cp.async.commit_group;" ::: "memory")
#define CP_WAIT(n)  asm volatile("cp.async.wait_group %0;" :: "n"(n) : "memory")

#define LDSM4(r0, r1, r2, r3, addr) \
    asm volatile("ldmatrix.sync.aligned.m8n8.x4.shared.b16 {%0,%1,%2,%3}, [%4];" \
                 : "=r"(r0), "=r"(r1), "=r"(r2), "=r"(r3) : "r"(addr))

#define MMA16816(d, a, b0, b1) \
    asm volatile("mma.sync.aligned.m16n8k16.row.col.f32.bf16.bf16.f32 " \
                 "{%0,%1,%2,%3}, {%4,%5,%6,%7}, {%8,%9}, {%0,%1,%2,%3};" \
                 : "+f"((d)[0]), "+f"((d)[1]), "+f"((d)[2]), "+f"((d)[3]) \
                 : "r"((a)[0]), "r"((a)[1]), "r"((a)[2]), "r"((a)[3]), \
                   "r"(b0), "r"(b1))

// fast exp on the FMA pipe (no MUFU). x <= ~0 expected (post max-subtract).
// 2^f minimax (Cephes), rel err ~1e-7 on f in [-0.5, 0.5].
__device__ __forceinline__ float fexp(float x) {
    float t = x * 1.44269504088896341f;
    t = fmaxf(t, -125.0f);
    float fi;
    asm("cvt.rni.f32.f32 %0, %1;" : "=f"(fi) : "f"(t));
    const float f = t - fi;
    float p = 1.535336188319500e-4f;
    p = fmaf(p, f, 1.339887440266574e-3f);
    p = fmaf(p, f, 9.618437357674640e-3f);
    p = fmaf(p, f, 5.550332471162809e-2f);
    p = fmaf(p, f, 2.402264791363012e-1f);
    p = fmaf(p, f, 6.931472028550421e-1f);
    p = fmaf(p, f, 1.0f);
    const int ei = (int)fi;
    const float s = __int_as_float((ei + 127) << 23);
    return p * s;
}

// ---------------- split-bf16 conversion ----------------
__device__ __forceinline__ uint32_t pk2(float x, float y) {
    __nv_bfloat162 t = __float22bfloat162_rn(make_float2(x, y));
    return *(uint32_t*)&t;
}
// activations: [M][256] f32 -> [M][768] bf16 as {hi, lo, hi}
template <int SRC>
__global__ __launch_bounds__(256) void conv_act(const float* __restrict__ srcp,
                                                __nv_bfloat16* __restrict__ dst) {
    const float* src = (SRC == 0) ? srcp : g_o;
    int i = blockIdx.x * 256 + threadIdx.x;       // float4 index, total MROWS*64
    float4 v = ((const float4*)src)[i];
    int row = i >> 6, c = (i & 63) << 2;
    __nv_bfloat16 hx = __float2bfloat16(v.x), hy = __float2bfloat16(v.y);
    __nv_bfloat16 hz = __float2bfloat16(v.z), hw = __float2bfloat16(v.w);
    float lx = v.x - __bfloat162float(hx), ly = v.y - __bfloat162float(hy);
    float lz = v.z - __bfloat162float(hz), lw = v.w - __bfloat162float(hw);
    uint2 hi; hi.x = pk2(__bfloat162float(hx), __bfloat162float(hy));
              hi.y = pk2(__bfloat162float(hz), __bfloat162float(hw));
    uint2 lo; lo.x = pk2(lx, ly); lo.y = pk2(lz, lw);
    __nv_bfloat16* base = dst + (size_t)row * KEXT + c;
    *(uint2*)(base)       = hi;
    *(uint2*)(base + 256) = lo;
    *(uint2*)(base + 512) = hi;
}
// weights: [N][256] f32 -> [N][768] bf16 as {hi, hi, lo}
__global__ __launch_bounds__(256) void conv_wgt(const float* __restrict__ src,
                                                __nv_bfloat16* __restrict__ dst) {
    int i = blockIdx.x * 256 + threadIdx.x;
    float4 v = ((const float4*)src)[i];
    int row = i >> 6, c = (i & 63) << 2;
    __nv_bfloat16 hx = __float2bfloat16(v.x), hy = __float2bfloat16(v.y);
    __nv_bfloat16 hz = __float2bfloat16(v.z), hw = __float2bfloat16(v.w);
    float lx = v.x - __bfloat162float(hx), ly = v.y - __bfloat162float(hy);
    float lz = v.z - __bfloat162float(hz), lw = v.w - __bfloat162float(hw);
    uint2 hi; hi.x = pk2(__bfloat162float(hx), __bfloat162float(hy));
              hi.y = pk2(__bfloat162float(hz), __bfloat162float(hw));
    uint2 lo; lo.x = pk2(lx, ly); lo.y = pk2(lz, lw);
    __nv_bfloat16* base = dst + (size_t)row * KEXT + c;
    *(uint2*)(base)       = hi;
    *(uint2*)(base + 256) = hi;
    *(uint2*)(base + 512) = lo;
}

// ---------------- HMMA bf16 GEMM (mma.sync.m16n8k16) ----------------
// Y[r][c] = sum_k A'[r][k] * B'[c][k]  (+bias), K = 768 split-bf16
// MODE 0: A=g_xb, B=g_wq -> scatter q/k/v ; MODE 1: A=g_ob, B=g_wp -> out
// CTA 128x128, BK=32, 24 stages, 4-deep cp.async pipeline, one barrier/stage,
// 8 warps 2(m)x4(n), __launch_bounds__(256,2) for 2 CTAs/SM.
#define BK     32
#define LDS_S  40                   // smem row stride in bf16 (padded)
#define NSTG   (KEXT / BK)          // 24
#define STAGEF (128 * LDS_S)        // bf16 per operand per stage (5120)
#define GSMEM  (4 * STAGEF * 2 * 2) // 81920 bytes

template <int MODE>
__global__ __launch_bounds__(256, 2) void hmma_gemm(const float* __restrict__ bias,
                                                    float* __restrict__ out) {
    extern __shared__ __align__(16) __nv_bfloat16 smb[];
    __nv_bfloat16* As = smb;                 // [4][STAGEF]
    __nv_bfloat16* Bs = smb + 4 * STAGEF;    // [4][STAGEF]

    const int tid = threadIdx.x, lane = tid & 31, wid = tid >> 5;
    const int nt = blockIdx.x;
    const int rowBase = blockIdx.y << 7;
    const int colBase = nt << 7;

    const __nv_bfloat16* Ag = ((MODE == 0) ? g_xb : g_ob) + (size_t)rowBase * KEXT;
    const __nv_bfloat16* Bg = ((MODE == 0) ? g_wq : g_wp) + (size_t)colBase * KEXT;

    // loader: 512 16B-chunks per operand per stage; thread t does chunks t, t+256
    const int c0r = tid >> 2, c0c = (tid & 3) << 3;           // chunk tid
    const int c1r = (tid + 256) >> 2, c1c = c0c;              // chunk tid+256

#define LOADSTAGE(s) do { \
    const int kt = (s) * BK; \
    __nv_bfloat16* ap = As + ((s) & 3) * STAGEF; \
    __nv_bfloat16* bp = Bs + ((s) & 3) * STAGEF; \
    CP16(s2u(ap + c0r * LDS_S + c0c), Ag + (size_t)c0r * KEXT + kt + c0c); \
    CP16(s2u(ap + c1r * LDS_S + c1c), Ag + (size_t)c1r * KEXT + kt + c1c); \
    CP16(s2u(bp + c0r * LDS_S + c0c), Bg + (size_t)c0r * KEXT + kt + c0c); \
    CP16(s2u(bp + c1r * LDS_S + c1c), Bg + (size_t)c1r * KEXT + kt + c1c); \
    CP_COMMIT(); \
} while (0)

    // warp tiling: 2 (m) x 4 (n); warp tile 64m x 32n
    const int wm = wid & 1, wn = wid >> 1;
    const int Am = wm * 64, Bn = wn * 32;
    // ldmatrix lane->tile coords
    const int a_row = lane & 15;
    const int a_ko  = (lane >> 4) << 3;
    const int b_n   = ((lane >> 4) << 3) + (lane & 7);
    const int b_ko  = ((lane >> 3) & 1) << 3;

    float d[4][4][4];
#pragma unroll
    for (int i = 0; i < 4; i++)
#pragma unroll
        for (int j = 0; j < 4; j++)
#pragma unroll
            for (int e = 0; e < 4; e++) d[i][j][e] = 0.f;

    LOADSTAGE(0);
    LOADSTAGE(1);
    LOADSTAGE(2);

    for (int s = 0; s < NSTG; s++) {
        if (s < NSTG - 2)       CP_WAIT(2);
        else if (s == NSTG - 2) CP_WAIT(1);
        else                    CP_WAIT(0);
        __syncthreads();

        const __nv_bfloat16* abuf = As + (s & 3) * STAGEF;
        const __nv_bfloat16* bbuf = Bs + (s & 3) * STAGEF;
#pragma unroll
        for (int kk = 0; kk < BK; kk += 16) {
            uint32_t a[4][4];
#pragma unroll
            for (int mi = 0; mi < 4; mi++) {
                const uint32_t ad =
                    s2u(abuf + (Am + mi * 16 + a_row) * LDS_S + kk + a_ko);
                LDSM4(a[mi][0], a[mi][1], a[mi][2], a[mi][3], ad);
            }
            uint32_t b[2][4];
#pragma unroll
            for (int nb = 0; nb < 2; nb++) {
                const uint32_t bd =
                    s2u(bbuf + (Bn + nb * 16 + b_n) * LDS_S + kk + b_ko);
                LDSM4(b[nb][0], b[nb][1], b[nb][2], b[nb][3], bd);
            }
#pragma unroll
            for (int mi = 0; mi < 4; mi++)
#pragma unroll
                for (int nj = 0; nj < 4; nj++)
                    MMA16816(d[mi][nj], a[mi], b[nj >> 1][(nj & 1) * 2],
                             b[nj >> 1][(nj & 1) * 2 + 1]);
        }
        // issue load for stage s+3 (buffer (s+3)&3 == (s-1)&3, safe: all warps
        // passed this stage's barrier, so none is still reading stage s-1)
        if (s + 3 < NSTG) LOADSTAGE(s + 3);
    }
#undef LOADSTAGE

    // epilogue
    const int erow = lane >> 2;          // 0..7
    const int ecol = (lane & 3) << 1;    // 0,2,4,6
#pragma unroll
    for (int mi = 0; mi < 4; mi++) {
#pragma unroll
        for (int nj = 0; nj < 4; nj++) {
            const int col = colBase + Bn + nj * 8 + ecol;   // even, pair in same head
            const float b0 = bias[col], b1 = bias[col + 1];
#pragma unroll
            for (int half = 0; half < 2; half++) {
                const int r = rowBase + Am + mi * 16 + erow + half * 8;
                float2 v;
                v.x = d[mi][nj][half * 2 + 0] + b0;
                v.y = d[mi][nj][half * 2 + 1] + b1;
                if (MODE == 0) {
                    const int sel = col >> 8, h = (col >> 5) & 7, dd = col & 31;
                    const int bb = r / NTOK, nn = r - bb * NTOK;
                    float* dst = (sel == 0) ? g_q : (sel == 1) ? g_k : g_v;
                    if (sel == 0) { v.x *= QSCALE; v.y *= QSCALE; }
                    *(float2*)&dst[(((size_t)bb * NH + h) * NTOK + nn) * HDIM + dd] = v;
                } else {
                    *(float2*)&out[(size_t)r * CDIM + col] = v;
                }
            }
        }
    }
}

// ---------------------------------------------------------------------------
// Fused attention: one CTA per (b, h), FFMA2 QK^T, polynomial exp (no MUFU).
// ---------------------------------------------------------------------------
#define FMA2(d, a, b, c) \
    asm("fma.rn.f32x2 %0, %1, %2, %3;" : "=l"(d) : "l"(a), "l"(b), "l"(c))
__device__ __forceinline__ ull pack2(float lo, float hi) {
    ull r; asm("mov.b64 %0, {%1, %2};" : "=l"(r) : "f"(lo), "f"(hi)); return r;
}
__device__ __forceinline__ float2 unpack2(ull v) {
    float2 f; asm("mov.b64 {%0, %1}, %2;" : "=f"(f.x), "=f"(f.y) : "l"(v)); return f;
}

#define SM_KT 0
#define SM_VS 6400
#define SM_BC 12672
#define SM_PB 13856
#define SM_QS 20256
#define SM_FLOATS 21280
#define ATTN_SMEM_BYTES (SM_FLOATS * 4)

__global__ __launch_bounds__(256) void attn_kernel(
    const float* __restrict__ mask, const float* __restrict__ bias_table,
    const int* __restrict__ rel_index)
{
    extern __shared__ float sm[];
    float* Kt = sm + SM_KT;
    float* Vs = sm + SM_VS;
    float* Bc = sm + SM_BC;

    const int tid = threadIdx.x;
    const int lane = tid & 31, warp = tid >> 5;
    const int bh = blockIdx.x;
    const int b = bh >> 3, h = bh & 7;
    const size_t base = (size_t)bh * (NTOK * HDIM);

    for (int idx = tid; idx < NTOK * HDIM; idx += 256) {
        const int m = idx >> 5, d = idx & 31;
        Kt[d * 200 + m] = g_k[base + idx];
        Vs[idx] = g_v[base + idx];
    }
    for (int i = tid; i < 1183; i += 256) Bc[i] = bias_table[i * NH + h];
    __syncthreads();

    const float4* Kt4 = (const float4*)Kt;
    const int* riB = rel_index;
    const float* mkB = mask + (size_t)(b & 63) * (NTOK * NTOK);
    const bool g2 = (lane < 17);
    float* Qw = sm + SM_QS + warp * 128;
    float* Pw = sm + SM_PB + warp * 800;
    const float4* Qw4 = (const float4*)Qw;

    for (int row0 = warp * 4; row0 < NTOK; row0 += 32) {
#pragma unroll
        for (int r = 0; r < 4; r++)
            Qw[r * 32 + lane] = g_q[base + (size_t)(row0 + r) * HDIM + lane];
        __syncwarp();

        ull S2[4][4] = {};
#pragma unroll
        for (int d4 = 0; d4 < 8; d4++) {
            float qa[4][4];
#pragma unroll
            for (int r = 0; r < 4; r++) {
                const float4 t = Qw4[r * 8 + d4];
                qa[r][0] = t.x; qa[r][1] = t.y; qa[r][2] = t.z; qa[r][3] = t.w;
            }
#pragma unroll
            for (int dd = 0; dd < 4; dd++) {
                const int d = d4 * 4 + dd;
                const float4 k0 = Kt4[d * 50 + lane];
                const ull kp0 = pack2(k0.x, k0.y);
                const ull kp1 = pack2(k0.z, k0.w);
                ull kp2 = 0, kp3 = 0;
                if (g2) {
                    const float4 k1 = Kt4[d * 50 + 32 + lane];
                    kp2 = pack2(k1.x, k1.y);
                    kp3 = pack2(k1.z, k1.w);
                }
#pragma unroll
                for (int r = 0; r < 4; r++) {
                    const ull q2 = pack2(qa[r][dd], qa[r][dd]);
                    FMA2(S2[r][0], q2, kp0, S2[r][0]);
                    FMA2(S2[r][1], q2, kp1, S2[r][1]);
                    if (g2) {
                        FMA2(S2[r][2], q2, kp2, S2[r][2]);
                        FMA2(S2[r][3], q2, kp3, S2[r][3]);
                    }
                }
            }
        }

        float S[4][8];
#pragma unroll
        for (int r = 0; r < 4; r++) {
#pragma unroll
            for (int p = 0; p < 4; p++) {
                const float2 u = unpack2(S2[r][p]);
                S[r][p * 2] = u.x; S[r][p * 2 + 1] = u.y;
            }
        }

#pragma unroll
        for (int r = 0; r < 4; r++) {
            const int row = row0 + r;
            {
                const int4   i0 = ((const int4*)(riB + row * NTOK))[lane];
                const float4 m0 = ((const float4*)(mkB + (size_t)row * NTOK))[lane];
                S[r][0] += Bc[i0.x] + m0.x; S[r][1] += Bc[i0.y] + m0.y;
                S[r][2] += Bc[i0.z] + m0.z; S[r][3] += Bc[i0.w] + m0.w;
                if (g2) {
                    const int4   i1 = ((const int4*)(riB + row * NTOK))[32 + lane];
                    const float4 m1 = ((const float4*)(mkB + (size_t)row * NTOK))[32 + lane];
                    S[r][4] += Bc[i1.x] + m1.x; S[r][5] += Bc[i1.y] + m1.y;
                    S[r][6] += Bc[i1.z] + m1.z; S[r][7] += Bc[i1.w] + m1.w;
                }
            }
            float mx = fmaxf(fmaxf(S[r][0], S[r][1]), fmaxf(S[r][2], S[r][3]));
            if (g2) mx = fmaxf(mx, fmaxf(fmaxf(S[r][4], S[r][5]), fmaxf(S[r][6], S[r][7])));
#pragma unroll
            for (int off = 16; off; off >>= 1)
                mx = fmaxf(mx, __shfl_xor_sync(0xffffffffu, mx, off));

            float sum = 0.f;
#pragma unroll
            for (int j = 0; j < 4; j++) { S[r][j] = fexp(S[r][j] - mx); sum += S[r][j]; }
            if (g2) {
#pragma unroll
                for (int j = 4; j < 8; j++) { S[r][j] = fexp(S[r][j] - mx); sum += S[r][j]; }
            }
#pragma unroll
            for (int off = 16; off; off >>= 1)
                sum += __shfl_xor_sync(0xffffffffu, sum, off);
            const float inv = 1.0f / sum;
#pragma unroll
            for (int j = 0; j < 8; j++) S[r][j] *= inv;

            ((float4*)(Pw + r * 200))[lane] = make_float4(S[r][0], S[r][1], S[r][2], S[r][3]);
            if (g2)
                ((float4*)(Pw + r * 200))[32 + lane] = make_float4(S[r][4], S[r][5], S[r][6], S[r][7]);
        }
        __syncwarp();

        float acc[4] = {0.f, 0.f, 0.f, 0.f};
#pragma unroll 7
        for (int g = 0; g < 49; g++) {
            const float* vr = Vs + g * 128 + lane;
            const float v0 = vr[0], v1 = vr[32], v2 = vr[64], v3 = vr[96];
#pragma unroll
            for (int r = 0; r < 4; r++) {
                const float4 p = ((const float4*)(Pw + r * 200))[g];
                acc[r] += p.x * v0 + p.y * v1 + p.z * v2 + p.w * v3;
            }
        }
#pragma unroll
        for (int r = 0; r < 4; r++)
            g_o[((size_t)b * NTOK + row0 + r) * CDIM + h * HDIM + lane] = acc[r];
        __syncwarp();
    }
}

// ---------------------------------------------------------------------------
extern "C" void kernel_launch(void* const* d_in, const int* in_sizes, int n_in,
                              void* d_out, int out_size)
{
    const float* x          = (const float*)d_in[0];
    const float* mask       = (const float*)d_in[1];
    const float* qkv_w      = (const float*)d_in[2];
    const float* qkv_b      = (const float*)d_in[3];
    const float* proj_w     = (const float*)d_in[4];
    const float* proj_b     = (const float*)d_in[5];
    const float* bias_table = (const float*)d_in[6];
    const int*   rel_index  = (const int*)d_in[7];
    float* out = (float*)d_out;

    cudaFuncSetAttribute(attn_kernel,
                         cudaFuncAttributeMaxDynamicSharedMemorySize, ATTN_SMEM_BYTES);
    cudaFuncSetAttribute(hmma_gemm<0>,
                         cudaFuncAttributeMaxDynamicSharedMemorySize, GSMEM);
    cudaFuncSetAttribute(hmma_gemm<1>,
                         cudaFuncAttributeMaxDynamicSharedMemorySize, GSMEM);

    __nv_bfloat16 *xb, *ob, *wq, *wp;
    cudaGetSymbolAddress((void**)&xb, g_xb);
    cudaGetSymbolAddress((void**)&ob, g_ob);
    cudaGetSymbolAddress((void**)&wq, g_wq);
    cudaGetSymbolAddress((void**)&wp, g_wp);

    // 1) split-bf16 conversions of x and weights
    conv_act<0><<<MROWS * 64 / 256, 256>>>(x, xb);
    conv_wgt<<<768 * 64 / 256, 256>>>(qkv_w, wq);
    conv_wgt<<<256 * 64 / 256, 256>>>(proj_w, wp);
    // 2) QKV projection (HMMA): N tiles 0..5 -> q (scaled), k, v
    hmma_gemm<0><<<dim3(6, MROWS / 128), 256, GSMEM>>>(qkv_b, nullptr);
    // 3) fused window attention -> g_o
    attn_kernel<<<B__ * NH, 256, ATTN_SMEM_BYTES>>>(mask, bias_table, rel_index);
    // 4) split-bf16 conversion of attention output
    conv_act<1><<<MROWS * 64 / 256, 256>>>(nullptr, ob);
    // 5) output projection (HMMA)
    hmma_gemm<1><<<dim3(2, MROWS / 128), 256, GSMEM>>>(proj_b, out);
}

// round 10
// speedup vs baseline: 1.3742x; 1.3742x over previous
#include <cuda_runtime.h>
#include <cuda_bf16.h>
#include <cstdint>

#define B__   256
#define NTOK  196
#define CDIM  256
#define NH    8
#define HDIM  32
#define MROWS (B__ * NTOK)          // 50176 = 392*128
#define KEXT  768                   // 3*256 split-bf16 K
#define QSCALE 0.17677669529663687f // 1/sqrt(32)

typedef unsigned long long ull;

// ---------------- scratch (device globals) ----------------
__device__ float g_q[MROWS * CDIM];
__device__ float g_k[MROWS * CDIM];
__device__ float g_v[MROWS * CDIM];
__device__ float g_o[MROWS * CDIM];
__device__ __nv_bfloat16 g_xb[(size_t)MROWS * KEXT]; // x split  [Ah, Al, Ah]
__device__ __nv_bfloat16 g_ob[(size_t)MROWS * KEXT]; // attn-out split
__device__ __nv_bfloat16 g_wq[768 * KEXT];           // qkv_w split [Bh, Bh, Bl]
__device__ __nv_bfloat16 g_wp[256 * KEXT];           // proj_w split

// ---------------- small PTX helpers ----------------
__device__ __forceinline__ uint32_t s2u(const void* p) {
    return (uint32_t)__cvta_generic_to_shared(p);
}
#define CP16(dst, src) \
    asm volatile("cp.async.ca.shared.global [%0], [%1], 16;" :: "r"(dst), "l"(src))
#define CP_COMMIT() asm volatile("cp.async.commit_group;" ::: "memory")
#define CP_WAIT(n)  asm volatile("cp.async.wait_group %0;" :: "n"(n) : "memory")

#define LDSM4(r0, r1, r2, r3, addr) \
    asm volatile("ldmatrix.sync.aligned.m8n8.x4.shared.b16 {%0,%1,%2,%3}, [%4];" \
                 : "=r"(r0), "=r"(r1), "=r"(r2), "=r"(r3) : "r"(addr))
#define LDSM4T(r0, r1, r2, r3, addr) \
    asm volatile("ldmatrix.sync.aligned.m8n8.x4.trans.shared.b16 {%0,%1,%2,%3}, [%4];" \
                 : "=r"(r0), "=r"(r1), "=r"(r2), "=r"(r3) : "r"(addr))

#define MMA16816(d, a, b0, b1) \
    asm volatile("mma.sync.aligned.m16n8k16.row.col.f32.bf16.bf16.f32 " \
                 "{%0,%1,%2,%3}, {%4,%5,%6,%7}, {%8,%9}, {%0,%1,%2,%3};" \
                 : "+f"((d)[0]), "+f"((d)[1]), "+f"((d)[2]), "+f"((d)[3]) \
                 : "r"((a)[0]), "r"((a)[1]), "r"((a)[2]), "r"((a)[3]), \
                   "r"(b0), "r"(b1))

// pack two f32 into bf16x2: lo half = first (even-k) element
__device__ __forceinline__ uint32_t bfpack(float lo, float hi) {
    uint32_t r;
    asm("cvt.rn.bf16x2.f32 %0, %1, %2;" : "=r"(r) : "f"(hi), "f"(lo));
    return r;
}

// ---------------- split-bf16 conversion ----------------
__device__ __forceinline__ uint32_t pk2(float x, float y) {
    __nv_bfloat162 t = __float22bfloat162_rn(make_float2(x, y));
    return *(uint32_t*)&t;
}
// activations: [M][256] f32 -> [M][768] bf16 as {hi, lo, hi}
template <int SRC>
__global__ __launch_bounds__(256) void conv_act(const float* __restrict__ srcp,
                                                __nv_bfloat16* __restrict__ dst) {
    const float* src = (SRC == 0) ? srcp : g_o;
    int i = blockIdx.x * 256 + threadIdx.x;       // float4 index, total MROWS*64
    float4 v = ((const float4*)src)[i];
    int row = i >> 6, c = (i & 63) << 2;
    __nv_bfloat16 hx = __float2bfloat16(v.x), hy = __float2bfloat16(v.y);
    __nv_bfloat16 hz = __float2bfloat16(v.z), hw = __float2bfloat16(v.w);
    float lx = v.x - __bfloat162float(hx), ly = v.y - __bfloat162float(hy);
    float lz = v.z - __bfloat162float(hz), lw = v.w - __bfloat162float(hw);
    uint2 hi; hi.x = pk2(__bfloat162float(hx), __bfloat162float(hy));
              hi.y = pk2(__bfloat162float(hz), __bfloat162float(hw));
    uint2 lo; lo.x = pk2(lx, ly); lo.y = pk2(lz, lw);
    __nv_bfloat16* base = dst + (size_t)row * KEXT + c;
    *(uint2*)(base)       = hi;
    *(uint2*)(base + 256) = lo;
    *(uint2*)(base + 512) = hi;
}
// weights: [N][256] f32 -> [N][768] bf16 as {hi, hi, lo}
__global__ __launch_bounds__(256) void conv_wgt(const float* __restrict__ src,
                                                __nv_bfloat16* __restrict__ dst) {
    int i = blockIdx.x * 256 + threadIdx.x;
    float4 v = ((const float4*)src)[i];
    int row = i >> 6, c = (i & 63) << 2;
    __nv_bfloat16 hx = __float2bfloat16(v.x), hy = __float2bfloat16(v.y);
    __nv_bfloat16 hz = __float2bfloat16(v.z), hw = __float2bfloat16(v.w);
    float lx = v.x - __bfloat162float(hx), ly = v.y - __bfloat162float(hy);
    float lz = v.z - __bfloat162float(hz), lw = v.w - __bfloat162float(hw);
    uint2 hi; hi.x = pk2(__bfloat162float(hx), __bfloat162float(hy));
              hi.y = pk2(__bfloat162float(hz), __bfloat162float(hw));
    uint2 lo; lo.x = pk2(lx, ly); lo.y = pk2(lz, lw);
    __nv_bfloat16* base = dst + (size_t)row * KEXT + c;
    *(uint2*)(base)       = hi;
    *(uint2*)(base + 256) = hi;
    *(uint2*)(base + 512) = lo;
}

// ---------------- HMMA bf16 GEMM (unchanged from R7) ----------------
#define BK     32
#define LDS_S  40
#define NSTG   (KEXT / BK)          // 24
#define STAGEF (128 * LDS_S)
#define GSMEM  (4 * STAGEF * 2 * 2) // 81920 bytes

template <int MODE>
__global__ __launch_bounds__(256, 2) void hmma_gemm(const float* __restrict__ bias,
                                                    float* __restrict__ out) {
    extern __shared__ __align__(16) __nv_bfloat16 smb[];
    __nv_bfloat16* As = smb;
    __nv_bfloat16* Bs = smb + 4 * STAGEF;

    const int tid = threadIdx.x, lane = tid & 31, wid = tid >> 5;
    const int nt = blockIdx.x;
    const int rowBase = blockIdx.y << 7;
    const int colBase = nt << 7;

    const __nv_bfloat16* Ag = ((MODE == 0) ? g_xb : g_ob) + (size_t)rowBase * KEXT;
    const __nv_bfloat16* Bg = ((MODE == 0) ? g_wq : g_wp) + (size_t)colBase * KEXT;

    const int c0r = tid >> 2, c0c = (tid & 3) << 3;
    const int c1r = (tid + 256) >> 2, c1c = c0c;

#define LOADSTAGE(s) do { \
    const int kt = (s) * BK; \
    __nv_bfloat16* ap = As + ((s) & 3) * STAGEF; \
    __nv_bfloat16* bp = Bs + ((s) & 3) * STAGEF; \
    CP16(s2u(ap + c0r * LDS_S + c0c), Ag + (size_t)c0r * KEXT + kt + c0c); \
    CP16(s2u(ap + c1r * LDS_S + c1c), Ag + (size_t)c1r * KEXT + kt + c1c); \
    CP16(s2u(bp + c0r * LDS_S + c0c), Bg + (size_t)c0r * KEXT + kt + c0c); \
    CP16(s2u(bp + c1r * LDS_S + c1c), Bg + (size_t)c1r * KEXT + kt + c1c); \
    CP_COMMIT(); \
} while (0)

    const int wm = wid & 1, wn = wid >> 1;
    const int Am = wm * 64, Bn = wn * 32;
    const int a_row = lane & 15;
    const int a_ko  = (lane >> 4) << 3;
    const int b_n   = ((lane >> 4) << 3) + (lane & 7);
    const int b_ko  = ((lane >> 3) & 1) << 3;

    float d[4][4][4];
#pragma unroll
    for (int i = 0; i < 4; i++)
#pragma unroll
        for (int j = 0; j < 4; j++)
#pragma unroll
            for (int e = 0; e < 4; e++) d[i][j][e] = 0.f;

    LOADSTAGE(0);
    LOADSTAGE(1);
    LOADSTAGE(2);

    for (int s = 0; s < NSTG; s++) {
        if (s < NSTG - 2)       CP_WAIT(2);
        else if (s == NSTG - 2) CP_WAIT(1);
        else                    CP_WAIT(0);
        __syncthreads();

        const __nv_bfloat16* abuf = As + (s & 3) * STAGEF;
        const __nv_bfloat16* bbuf = Bs + (s & 3) * STAGEF;
#pragma unroll
        for (int kk = 0; kk < BK; kk += 16) {
            uint32_t a[4][4];
#pragma unroll
            for (int mi = 0; mi < 4; mi++) {
                const uint32_t ad =
                    s2u(abuf + (Am + mi * 16 + a_row) * LDS_S + kk + a_ko);
                LDSM4(a[mi][0], a[mi][1], a[mi][2], a[mi][3], ad);
            }
            uint32_t b[2][4];
#pragma unroll
            for (int nb = 0; nb < 2; nb++) {
                const uint32_t bd =
                    s2u(bbuf + (Bn + nb * 16 + b_n) * LDS_S + kk + b_ko);
                LDSM4(b[nb][0], b[nb][1], b[nb][2], b[nb][3], bd);
            }
#pragma unroll
            for (int mi = 0; mi < 4; mi++)
#pragma unroll
                for (int nj = 0; nj < 4; nj++)
                    MMA16816(d[mi][nj], a[mi], b[nj >> 1][(nj & 1) * 2],
                             b[nj >> 1][(nj & 1) * 2 + 1]);
        }
        if (s + 3 < NSTG) LOADSTAGE(s + 3);
    }
#undef LOADSTAGE

    const int erow = lane >> 2;
    const int ecol = (lane & 3) << 1;
#pragma unroll
    for (int mi = 0; mi < 4; mi++) {
#pragma unroll
        for (int nj = 0; nj < 4; nj++) {
            const int col = colBase + Bn + nj * 8 + ecol;
            const float b0 = bias[col], b1 = bias[col + 1];
#pragma unroll
            for (int half = 0; half < 2; half++) {
                const int r = rowBase + Am + mi * 16 + erow + half * 8;
                float2 v;
                v.x = d[mi][nj][half * 2 + 0] + b0;
                v.y = d[mi][nj][half * 2 + 1] + b1;
                if (MODE == 0) {
                    const int sel = col >> 8, h = (col >> 5) & 7, dd = col & 31;
                    const int bb = r / NTOK, nn = r - bb * NTOK;
                    float* dst = (sel == 0) ? g_q : (sel == 1) ? g_k : g_v;
                    if (sel == 0) { v.x *= QSCALE; v.y *= QSCALE; }
                    *(float2*)&dst[(((size_t)bb * NH + h) * NTOK + nn) * HDIM + dd] = v;
                } else {
                    *(float2*)&out[(size_t)r * CDIM + col] = v;
                }
            }
        }
    }
}

// ---------------- HMMA flash attention ----------------
// CTA = one (b,h); 4 warps; M padded 196->208 (13 m16 tiles), N padded 208.
// QK^T: 3-term split bf16 (QhKh + QlKh + QhKl), fp32 accum.
// softmax in fragment registers; P split hi/lo in regs; PV: PhVh + PlVh + PhVl.
#define AT_S   72                          // smem row stride (bf16), conflict-free
#define AROWS  208
#define ASMEM_BYTES (3 * AROWS * AT_S * 2 + 1184 * 4)   // 94592

__global__ __launch_bounds__(128, 2) void attn_mma(
    const float* __restrict__ mask, const float* __restrict__ bias_table,
    const int* __restrict__ rel_index)
{
    extern __shared__ __align__(16) __nv_bfloat16 smb[];
    __nv_bfloat16* Qs = smb;
    __nv_bfloat16* Ks = smb + AROWS * AT_S;
    __nv_bfloat16* Vs = smb + 2 * AROWS * AT_S;
    float* Bc = (float*)(smb + 3 * AROWS * AT_S);

    const int tid = threadIdx.x, lane = tid & 31, wid = tid >> 5;
    const int bh = blockIdx.x, b = bh >> 3, h = bh & 7;
    const size_t base = (size_t)bh * (NTOK * HDIM);

    // zero pad rows 196..207 (cols 0..63 used by ldmatrix)
    for (int i = tid; i < 12 * 64; i += 128) {
        const int r = 196 + (i >> 6), c = i & 63;
        const __nv_bfloat16 z = __float2bfloat16(0.f);
        Qs[r * AT_S + c] = z; Ks[r * AT_S + c] = z; Vs[r * AT_S + c] = z;
    }
    // load + split q/k/v (q pre-scaled by gemm0)
    for (int i = tid; i < NTOK * HDIM; i += 128) {
        const int r = i >> 5, d = i & 31;
        const float q = g_q[base + i], k = g_k[base + i], v = g_v[base + i];
        const __nv_bfloat16 qh = __float2bfloat16(q);
        const __nv_bfloat16 kh = __float2bfloat16(k);
        const __nv_bfloat16 vh = __float2bfloat16(v);
        Qs[r * AT_S + d] = qh; Qs[r * AT_S + 32 + d] = __float2bfloat16(q - __bfloat162float(qh));
        Ks[r * AT_S + d] = kh; Ks[r * AT_S + 32 + d] = __float2bfloat16(k - __bfloat162float(kh));
        Vs[r * AT_S + d] = vh; Vs[r * AT_S + 32 + d] = __float2bfloat16(v - __bfloat162float(vh));
    }
    for (int i = tid; i < 1183; i += 128) Bc[i] = bias_table[i * NH + h];
    __syncthreads();

    const uint32_t Qsu = s2u(Qs), Ksu = s2u(Ks), Vsu = s2u(Vs);
    const int* relB = rel_index;
    const float* mkB = mask + (size_t)(b & 63) * (NTOK * NTOK);

    // ldmatrix lane coords (identical to the passing gemm)
    const int a_row = lane & 15;
    const int a_ko  = (lane >> 4) << 3;
    const int b_n   = ((lane >> 4) << 3) + (lane & 7);
    const int b_ko  = ((lane >> 3) & 1) << 3;

    for (int mt = wid; mt < 13; mt += 4) {
        const int mb = mt * 16;

        // Q A-fragments for k-chunks d0-15(h), d16-31(h), d0-15(l), d16-31(l)
        uint32_t aq[4][4];
#pragma unroll
        for (int kt = 0; kt < 4; kt++) {
            const uint32_t ad = Qsu + ((mb + a_row) * AT_S + kt * 16 + a_ko) * 2;
            LDSM4(aq[kt][0], aq[kt][1], aq[kt][2], aq[kt][3], ad);
        }

        float S[26][4];
#pragma unroll
        for (int nt = 0; nt < 26; nt++)
#pragma unroll
            for (int e = 0; e < 4; e++) S[nt][e] = 0.f;

        // QK^T
#pragma unroll
        for (int n16 = 0; n16 < 13; n16++) {
            const int nb = n16 * 16;
            uint32_t bk[4][4];
#pragma unroll
            for (int kt = 0; kt < 4; kt++) {
                const uint32_t bd = Ksu + ((nb + b_n) * AT_S + kt * 16 + b_ko) * 2;
                LDSM4(bk[kt][0], bk[kt][1], bk[kt][2], bk[kt][3], bd);
            }
            // term pairs (A,B): QhKh:(0,0)(1,1)  QlKh:(2,0)(3,1)  QhKl:(0,2)(1,3)
            const int pa[6] = {0, 1, 2, 3, 0, 1};
            const int pb[6] = {0, 1, 0, 1, 2, 3};
#pragma unroll
            for (int t = 0; t < 6; t++) {
                MMA16816(S[2 * n16],     aq[pa[t]], bk[pb[t]][0], bk[pb[t]][1]);
                MMA16816(S[2 * n16 + 1], aq[pa[t]], bk[pb[t]][2], bk[pb[t]][3]);
            }
        }

        // bias + mask (fragment addressing), pad cols -> -1e9
        const int r0 = mb + (lane >> 2), r1 = r0 + 8;
        const int r0e = min(r0, 195), r1e = min(r1, 195);
#pragma unroll
        for (int nt = 0; nt < 26; nt++) {
            const int c = nt * 8 + ((lane & 3) << 1);
            const int ce = min(c, 194);
            const int2   i0 = *(const int2*)(relB + r0e * NTOK + ce);
            const int2   i1 = *(const int2*)(relB + r1e * NTOK + ce);
            const float2 m0 = *(const float2*)(mkB + (size_t)r0e * NTOK + ce);
            const float2 m1 = *(const float2*)(mkB + (size_t)r1e * NTOK + ce);
            S[nt][0] += Bc[i0.x] + m0.x; S[nt][1] += Bc[i0.y] + m0.y;
            S[nt][2] += Bc[i1.x] + m1.x; S[nt][3] += Bc[i1.y] + m1.y;
            if (c >= NTOK) { S[nt][0] = S[nt][1] = S[nt][2] = S[nt][3] = -1e9f; }
        }

        // softmax (rows r0: elems 0,1 ; rows r1: elems 2,3) — quad reduction
        float mx0 = -1e30f, mx1 = -1e30f;
#pragma unroll
        for (int nt = 0; nt < 26; nt++) {
            mx0 = fmaxf(mx0, fmaxf(S[nt][0], S[nt][1]));
            mx1 = fmaxf(mx1, fmaxf(S[nt][2], S[nt][3]));
        }
        mx0 = fmaxf(mx0, __shfl_xor_sync(0xffffffffu, mx0, 1));
        mx0 = fmaxf(mx0, __shfl_xor_sync(0xffffffffu, mx0, 2));
        mx1 = fmaxf(mx1, __shfl_xor_sync(0xffffffffu, mx1, 1));
        mx1 = fmaxf(mx1, __shfl_xor_sync(0xffffffffu, mx1, 2));
        float s0 = 0.f, s1 = 0.f;
#pragma unroll
        for (int nt = 0; nt < 26; nt++) {
            S[nt][0] = __expf(S[nt][0] - mx0); S[nt][1] = __expf(S[nt][1] - mx0);
            S[nt][2] = __expf(S[nt][2] - mx1); S[nt][3] = __expf(S[nt][3] - mx1);
            s0 += S[nt][0] + S[nt][1];
            s1 += S[nt][2] + S[nt][3];
        }
        s0 += __shfl_xor_sync(0xffffffffu, s0, 1);
        s0 += __shfl_xor_sync(0xffffffffu, s0, 2);
        s1 += __shfl_xor_sync(0xffffffffu, s1, 1);
        s1 += __shfl_xor_sync(0xffffffffu, s1, 2);
        const float inv0 = 1.0f / s0, inv1 = 1.0f / s1;

        // PV: O[m16 x d32]  (unnormalized P; normalize at store)
        float O[4][4];
#pragma unroll
        for (int j = 0; j < 4; j++)
#pragma unroll
            for (int e = 0; e < 4; e++) O[j][e] = 0.f;

#pragma unroll
        for (int kt = 0; kt < 13; kt++) {
            // build P hi/lo A-fragments from S[2kt], S[2kt+1]
            uint32_t ph[4], pl[4];
#pragma unroll
            for (int half = 0; half < 2; half++) {   // a0/a1 from S[2kt], a2/a3 from S[2kt+1]
                const float e0 = S[2 * kt + half][0], e1 = S[2 * kt + half][1];
                const float e2 = S[2 * kt + half][2], e3 = S[2 * kt + half][3];
                const uint32_t h01 = bfpack(e0, e1);
                const uint32_t h23 = bfpack(e2, e3);
                const float f0 = __uint_as_float(h01 << 16);
                const float f1 = __uint_as_float(h01 & 0xffff0000u);
                const float f2 = __uint_as_float(h23 << 16);
                const float f3 = __uint_as_float(h23 & 0xffff0000u);
                ph[half * 2 + 0] = h01;                       // (row r0, k even/odd)
                ph[half * 2 + 1] = h23;                       // (row r1)
                pl[half * 2 + 0] = bfpack(e0 - f0, e1 - f1);
                pl[half * 2 + 1] = bfpack(e2 - f2, e3 - f3);
            }
            // A frag order: a0=(r0,k0-7 of S[2kt]), a1=(r1,..), a2/a3 from S[2kt+1] (k8-15)
            uint32_t pa_h[4] = {ph[0], ph[1], ph[2], ph[3]};
            uint32_t pa_l[4] = {pl[0], pl[1], pl[2], pl[3]};

            // V B-fragments via ldmatrix.trans: rows = tokens (k), cols = d (n)
            uint32_t vh[2][4], vl[2][4];
#pragma unroll
            for (int g = 0; g < 2; g++) {            // d group 0-15 / 16-31
                const uint32_t vda =
                    Vsu + ((kt * 16 + (lane & 15)) * AT_S + g * 16 + ((lane >> 4) << 3)) * 2;
                LDSM4T(vh[g][0], vh[g][1], vh[g][2], vh[g][3], vda);
                const uint32_t vdl = vda + 32 * 2;   // Vl at col offset +32
                LDSM4T(vl[g][0], vl[g][1], vl[g][2], vl[g][3], vdl);
            }
#pragma unroll
            for (int g = 0; g < 2; g++) {
                MMA16816(O[g * 2 + 0], pa_h, vh[g][0], vh[g][1]);
                MMA16816(O[g * 2 + 1], pa_h, vh[g][2], vh[g][3]);
                MMA16816(O[g * 2 + 0], pa_l, vh[g][0], vh[g][1]);
                MMA16816(O[g * 2 + 1], pa_l, vh[g][2], vh[g][3]);
                MMA16816(O[g * 2 + 0], pa_h, vl[g][0], vl[g][1]);
                MMA16816(O[g * 2 + 1], pa_h, vl[g][2], vl[g][3]);
            }
        }

        // store (normalize)
        const int dcol = (lane & 3) << 1;
        if (r0 < NTOK) {
            float* op = g_o + ((size_t)b * NTOK + r0) * CDIM + h * HDIM + dcol;
#pragma unroll
            for (int j = 0; j < 4; j++)
                *(float2*)(op + j * 8) = make_float2(O[j][0] * inv0, O[j][1] * inv0);
        }
        if (r1 < NTOK) {
            float* op = g_o + ((size_t)b * NTOK + r1) * CDIM + h * HDIM + dcol;
#pragma unroll
            for (int j = 0; j < 4; j++)
                *(float2*)(op + j * 8) = make_float2(O[j][2] * inv1, O[j][3] * inv1);
        }
    }
}

// ---------------------------------------------------------------------------
extern "C" void kernel_launch(void* const* d_in, const int* in_sizes, int n_in,
                              void* d_out, int out_size)
{
    const float* x          = (const float*)d_in[0];
    const float* mask       = (const float*)d_in[1];
    const float* qkv_w      = (const float*)d_in[2];
    const float* qkv_b      = (const float*)d_in[3];
    const float* proj_w     = (const float*)d_in[4];
    const float* proj_b     = (const float*)d_in[5];
    const float* bias_table = (const float*)d_in[6];
    const int*   rel_index  = (const int*)d_in[7];
    float* out = (float*)d_out;

    cudaFuncSetAttribute(attn_mma,
                         cudaFuncAttributeMaxDynamicSharedMemorySize, ASMEM_BYTES);
    cudaFuncSetAttribute(hmma_gemm<0>,
                         cudaFuncAttributeMaxDynamicSharedMemorySize, GSMEM);
    cudaFuncSetAttribute(hmma_gemm<1>,
                         cudaFuncAttributeMaxDynamicSharedMemorySize, GSMEM);

    __nv_bfloat16 *xb, *ob, *wq, *wp;
    cudaGetSymbolAddress((void**)&xb, g_xb);
    cudaGetSymbolAddress((void**)&ob, g_ob);
    cudaGetSymbolAddress((void**)&wq, g_wq);
    cudaGetSymbolAddress((void**)&wp, g_wp);

    // 1) split-bf16 conversions of x and weights
    conv_act<0><<<MROWS * 64 / 256, 256>>>(x, xb);
    conv_wgt<<<768 * 64 / 256, 256>>>(qkv_w, wq);
    conv_wgt<<<256 * 64 / 256, 256>>>(proj_w, wp);
    // 2) QKV projection (HMMA): N tiles 0..5 -> q (scaled), k, v
    hmma_gemm<0><<<dim3(6, MROWS / 128), 256, GSMEM>>>(qkv_b, nullptr);
    // 3) HMMA flash attention -> g_o
    attn_mma<<<B__ * NH, 128, ASMEM_BYTES>>>(mask, bias_table, rel_index);
    // 4) split-bf16 conversion of attention output
    conv_act<1><<<MROWS * 64 / 256, 256>>>(nullptr, ob);
    // 5) output projection (HMMA)
    hmma_gemm<1><<<dim3(2, MROWS / 128), 256, GSMEM>>>(proj_b, out);
}

// round 11
// speedup vs baseline: 1.5353x; 1.1173x over previous
#include <cuda_runtime.h>
#include <cuda_bf16.h>
#include <cstdint>

#define B__   256
#define NTOK  196
#define CDIM  256
#define NH    8
#define HDIM  32
#define MROWS (B__ * NTOK)          // 50176 = 392*128
#define KEXT  768                   // 3*256 split-bf16 K
#define QSCALE 0.17677669529663687f // 1/sqrt(32)

typedef unsigned long long ull;

// ---------------- scratch (device globals) ----------------
__device__ float g_q[MROWS * CDIM];
__device__ float g_k[MROWS * CDIM];
__device__ float g_v[MROWS * CDIM];
__device__ float g_bm[NH * NTOK * NTOK];             // bias gathered per head
__device__ __nv_bfloat16 g_xb[(size_t)MROWS * KEXT]; // x split  [Ah, Al, Ah]
__device__ __nv_bfloat16 g_ob[(size_t)MROWS * KEXT]; // attn-out split
__device__ __nv_bfloat16 g_wq[768 * KEXT];           // qkv_w split [Bh, Bh, Bl]
__device__ __nv_bfloat16 g_wp[256 * KEXT];           // proj_w split

// ---------------- small PTX helpers ----------------
__device__ __forceinline__ uint32_t s2u(const void* p) {
    return (uint32_t)__cvta_generic_to_shared(p);
}
#define CP16(dst, src) \
    asm volatile("cp.async.ca.shared.global [%0], [%1], 16;" :: "r"(dst), "l"(src))
#define CP_COMMIT() asm volatile("cp.async.commit_group;" ::: "memory")
#define CP_WAIT(n)  asm volatile("cp.async.wait_group %0;" :: "n"(n) : "memory")

#define LDSM4(r0, r1, r2, r3, addr) \
    asm volatile("ldmatrix.sync.aligned.m8n8.x4.shared.b16 {%0,%1,%2,%3}, [%4];" \
                 : "=r"(r0), "=r"(r1), "=r"(r2), "=r"(r3) : "r"(addr))
#define LDSM4T(r0, r1, r2, r3, addr) \
    asm volatile("ldmatrix.sync.aligned.m8n8.x4.trans.shared.b16 {%0,%1,%2,%3}, [%4];" \
                 : "=r"(r0), "=r"(r1), "=r"(r2), "=r"(r3) : "r"(addr))

#define MMA16816(d, a, b0, b1) \
    asm volatile("mma.sync.aligned.m16n8k16.row.col.f32.bf16.bf16.f32 " \
                 "{%0,%1,%2,%3}, {%4,%5,%6,%7}, {%8,%9}, {%0,%1,%2,%3};" \
                 : "+f"((d)[0]), "+f"((d)[1]), "+f"((d)[2]), "+f"((d)[3]) \
                 : "r"((a)[0]), "r"((a)[1]), "r"((a)[2]), "r"((a)[3]), \
                   "r"(b0), "r"(b1))

// pack two f32 into bf16x2: first arg -> low half
__device__ __forceinline__ uint32_t bfpack(float lo, float hi) {
    uint32_t r;
    asm("cvt.rn.bf16x2.f32 %0, %1, %2;" : "=r"(r) : "f"(hi), "f"(lo));
    return r;
}

// ---------------- split-bf16 conversion ----------------
__device__ __forceinline__ uint32_t pk2(float x, float y) {
    __nv_bfloat162 t = __float22bfloat162_rn(make_float2(x, y));
    return *(uint32_t*)&t;
}
// activations: [M][256] f32 -> [M][768] bf16 as {hi, lo, hi}
__global__ __launch_bounds__(256) void conv_act(const float* __restrict__ src,
                                                __nv_bfloat16* __restrict__ dst) {
    int i = blockIdx.x * 256 + threadIdx.x;       // float4 index, total MROWS*64
    float4 v = ((const float4*)src)[i];
    int row = i >> 6, c = (i & 63) << 2;
    __nv_bfloat16 hx = __float2bfloat16(v.x), hy = __float2bfloat16(v.y);
    __nv_bfloat16 hz = __float2bfloat16(v.z), hw = __float2bfloat16(v.w);
    float lx = v.x - __bfloat162float(hx), ly = v.y - __bfloat162float(hy);
    float lz = v.z - __bfloat162float(hz), lw = v.w - __bfloat162float(hw);
    uint2 hi; hi.x = pk2(__bfloat162float(hx), __bfloat162float(hy));
              hi.y = pk2(__bfloat162float(hz), __bfloat162float(hw));
    uint2 lo; lo.x = pk2(lx, ly); lo.y = pk2(lz, lw);
    __nv_bfloat16* base = dst + (size_t)row * KEXT + c;
    *(uint2*)(base)       = hi;
    *(uint2*)(base + 256) = lo;
    *(uint2*)(base + 512) = hi;
}
// weights: [N][256] f32 -> [N][768] bf16 as {hi, hi, lo}
__global__ __launch_bounds__(256) void conv_wgt(const float* __restrict__ src,
                                                __nv_bfloat16* __restrict__ dst) {
    int i = blockIdx.x * 256 + threadIdx.x;
    float4 v = ((const float4*)src)[i];
    int row = i >> 6, c = (i & 63) << 2;
    __nv_bfloat16 hx = __float2bfloat16(v.x), hy = __float2bfloat16(v.y);
    __nv_bfloat16 hz = __float2bfloat16(v.z), hw = __float2bfloat16(v.w);
    float lx = v.x - __bfloat162float(hx), ly = v.y - __bfloat162float(hy);
    float lz = v.z - __bfloat162float(hz), lw = v.w - __bfloat162float(hw);
    uint2 hi; hi.x = pk2(__bfloat162float(hx), __bfloat162float(hy));
              hi.y = pk2(__bfloat162float(hz), __bfloat162float(hw));
    uint2 lo; lo.x = pk2(lx, ly); lo.y = pk2(lz, lw);
    __nv_bfloat16* base = dst + (size_t)row * KEXT + c;
    *(uint2*)(base)       = hi;
    *(uint2*)(base + 256) = hi;
    *(uint2*)(base + 512) = lo;
}

// bias gather precompute: g_bm[h][n][m] = bias_table[rel_index[n*196+m]][h]
__global__ __launch_bounds__(256) void bias_pre(const float* __restrict__ bt,
                                                const int* __restrict__ ri) {
    int i = blockIdx.x * 256 + threadIdx.x;
    if (i < NTOK * NTOK) {
        const int idx = ri[i];
#pragma unroll
        for (int h = 0; h < NH; h++)
            g_bm[h * (NTOK * NTOK) + i] = bt[idx * NH + h];
    }
}

// ---------------- HMMA bf16 GEMM (unchanged from R7) ----------------
#define BK     32
#define LDS_S  40
#define NSTG   (KEXT / BK)          // 24
#define STAGEF (128 * LDS_S)
#define GSMEM  (4 * STAGEF * 2 * 2) // 81920 bytes

template <int MODE>
__global__ __launch_bounds__(256, 2) void hmma_gemm(const float* __restrict__ bias,
                                                    float* __restrict__ out) {
    extern __shared__ __align__(16) __nv_bfloat16 smb[];
    __nv_bfloat16* As = smb;
    __nv_bfloat16* Bs = smb + 4 * STAGEF;

    const int tid = threadIdx.x, lane = tid & 31, wid = tid >> 5;
    const int nt = blockIdx.x;
    const int rowBase = blockIdx.y << 7;
    const int colBase = nt << 7;

    const __nv_bfloat16* Ag = ((MODE == 0) ? g_xb : g_ob) + (size_t)rowBase * KEXT;
    const __nv_bfloat16* Bg = ((MODE == 0) ? g_wq : g_wp) + (size_t)colBase * KEXT;

    const int c0r = tid >> 2, c0c = (tid & 3) << 3;
    const int c1r = (tid + 256) >> 2, c1c = c0c;

#define LOADSTAGE(s) do { \
    const int kt = (s) * BK; \
    __nv_bfloat16* ap = As + ((s) & 3) * STAGEF; \
    __nv_bfloat16* bp = Bs + ((s) & 3) * STAGEF; \
    CP16(s2u(ap + c0r * LDS_S + c0c), Ag + (size_t)c0r * KEXT + kt + c0c); \
    CP16(s2u(ap + c1r * LDS_S + c1c), Ag + (size_t)c1r * KEXT + kt + c1c); \
    CP16(s2u(bp + c0r * LDS_S + c0c), Bg + (size_t)c0r * KEXT + kt + c0c); \
    CP16(s2u(bp + c1r * LDS_S + c1c), Bg + (size_t)c1r * KEXT + kt + c1c); \
    CP_COMMIT(); \
} while (0)

    const int wm = wid & 1, wn = wid >> 1;
    const int Am = wm * 64, Bn = wn * 32;
    const int a_row = lane & 15;
    const int a_ko  = (lane >> 4) << 3;
    const int b_n   = ((lane >> 4) << 3) + (lane & 7);
    const int b_ko  = ((lane >> 3) & 1) << 3;

    float d[4][4][4];
#pragma unroll
    for (int i = 0; i < 4; i++)
#pragma unroll
        for (int j = 0; j < 4; j++)
#pragma unroll
            for (int e = 0; e < 4; e++) d[i][j][e] = 0.f;

    LOADSTAGE(0);
    LOADSTAGE(1);
    LOADSTAGE(2);

    for (int s = 0; s < NSTG; s++) {
        if (s < NSTG - 2)       CP_WAIT(2);
        else if (s == NSTG - 2) CP_WAIT(1);
        else                    CP_WAIT(0);
        __syncthreads();

        const __nv_bfloat16* abuf = As + (s & 3) * STAGEF;
        const __nv_bfloat16* bbuf = Bs + (s & 3) * STAGEF;
#pragma unroll
        for (int kk = 0; kk < BK; kk += 16) {
            uint32_t a[4][4];
#pragma unroll
            for (int mi = 0; mi < 4; mi++) {
                const uint32_t ad =
                    s2u(abuf + (Am + mi * 16 + a_row) * LDS_S + kk + a_ko);
                LDSM4(a[mi][0], a[mi][1], a[mi][2], a[mi][3], ad);
            }
            uint32_t b[2][4];
#pragma unroll
            for (int nb = 0; nb < 2; nb++) {
                const uint32_t bd =
                    s2u(bbuf + (Bn + nb * 16 + b_n) * LDS_S + kk + b_ko);
                LDSM4(b[nb][0], b[nb][1], b[nb][2], b[nb][3], bd);
            }
#pragma unroll
            for (int mi = 0; mi < 4; mi++)
#pragma unroll
                for (int nj = 0; nj < 4; nj++)
                    MMA16816(d[mi][nj], a[mi], b[nj >> 1][(nj & 1) * 2],
                             b[nj >> 1][(nj & 1) * 2 + 1]);
        }
        if (s + 3 < NSTG) LOADSTAGE(s + 3);
    }
#undef LOADSTAGE

    const int erow = lane >> 2;
    const int ecol = (lane & 3) << 1;
#pragma unroll
    for (int mi = 0; mi < 4; mi++) {
#pragma unroll
        for (int nj = 0; nj < 4; nj++) {
            const int col = colBase + Bn + nj * 8 + ecol;
            const float b0 = bias[col], b1 = bias[col + 1];
#pragma unroll
            for (int half = 0; half < 2; half++) {
                const int r = rowBase + Am + mi * 16 + erow + half * 8;
                float2 v;
                v.x = d[mi][nj][half * 2 + 0] + b0;
                v.y = d[mi][nj][half * 2 + 1] + b1;
                if (MODE == 0) {
                    const int sel = col >> 8, h = (col >> 5) & 7, dd = col & 31;
                    const int bb = r / NTOK, nn = r - bb * NTOK;
                    float* dst = (sel == 0) ? g_q : (sel == 1) ? g_k : g_v;
                    if (sel == 0) { v.x *= QSCALE; v.y *= QSCALE; }
                    *(float2*)&dst[(((size_t)bb * NH + h) * NTOK + nn) * HDIM + dd] = v;
                } else {
                    *(float2*)&out[(size_t)r * CDIM + col] = v;
                }
            }
        }
    }
}

// ---------------- HMMA flash attention ----------------
// CTA = one (b,h); 4 warps; M padded 196->208 (13 m16 tiles), N padded 208.
// QK^T: 3-term split bf16; softmax in regs; PV: PhVh + PlVh + PhVl.
// bias via precomputed g_bm (coalesced f2 LDG); stores split-bf16 into g_ob.
#define AT_S   72                          // smem row stride (bf16), conflict-free
#define AROWS  208
#define ASMEM_BYTES (3 * AROWS * AT_S * 2)  // 89856

__global__ __launch_bounds__(128, 2) void attn_mma(
    const float* __restrict__ mask)
{
    extern __shared__ __align__(16) __nv_bfloat16 smb[];
    __nv_bfloat16* Qs = smb;
    __nv_bfloat16* Ks = smb + AROWS * AT_S;
    __nv_bfloat16* Vs = smb + 2 * AROWS * AT_S;

    const int tid = threadIdx.x, lane = tid & 31, wid = tid >> 5;
    const int bh = blockIdx.x, b = bh >> 3, h = bh & 7;
    const size_t base = (size_t)bh * (NTOK * HDIM);

    // zero pad rows 196..207 (cols 0..63 used by ldmatrix)
    for (int i = tid; i < 12 * 64; i += 128) {
        const int r = 196 + (i >> 6), c = i & 63;
        const __nv_bfloat16 z = __float2bfloat16(0.f);
        Qs[r * AT_S + c] = z; Ks[r * AT_S + c] = z; Vs[r * AT_S + c] = z;
    }
    // load + split q/k/v (q pre-scaled by gemm0)
    for (int i = tid; i < NTOK * HDIM; i += 128) {
        const int r = i >> 5, d = i & 31;
        const float q = g_q[base + i], k = g_k[base + i], v = g_v[base + i];
        const __nv_bfloat16 qh = __float2bfloat16(q);
        const __nv_bfloat16 kh = __float2bfloat16(k);
        const __nv_bfloat16 vh = __float2bfloat16(v);
        Qs[r * AT_S + d] = qh; Qs[r * AT_S + 32 + d] = __float2bfloat16(q - __bfloat162float(qh));
        Ks[r * AT_S + d] = kh; Ks[r * AT_S + 32 + d] = __float2bfloat16(k - __bfloat162float(kh));
        Vs[r * AT_S + d] = vh; Vs[r * AT_S + 32 + d] = __float2bfloat16(v - __bfloat162float(vh));
    }
    __syncthreads();

    const uint32_t Qsu = s2u(Qs), Ksu = s2u(Ks), Vsu = s2u(Vs);
    const float* bmB = g_bm + h * (NTOK * NTOK);
    const float* mkB = mask + (size_t)(b & 63) * (NTOK * NTOK);

    // ldmatrix lane coords (identical to the passing gemm)
    const int a_row = lane & 15;
    const int a_ko  = (lane >> 4) << 3;
    const int b_n   = ((lane >> 4) << 3) + (lane & 7);
    const int b_ko  = ((lane >> 3) & 1) << 3;

    for (int mt = wid; mt < 13; mt += 4) {
        const int mb = mt * 16;

        // Q A-fragments for k-chunks d0-15(h), d16-31(h), d0-15(l), d16-31(l)
        uint32_t aq[4][4];
#pragma unroll
        for (int kt = 0; kt < 4; kt++) {
            const uint32_t ad = Qsu + ((mb + a_row) * AT_S + kt * 16 + a_ko) * 2;
            LDSM4(aq[kt][0], aq[kt][1], aq[kt][2], aq[kt][3], ad);
        }

        float S[26][4];
#pragma unroll
        for (int nt = 0; nt < 26; nt++)
#pragma unroll
            for (int e = 0; e < 4; e++) S[nt][e] = 0.f;

        // QK^T
#pragma unroll
        for (int n16 = 0; n16 < 13; n16++) {
            const int nb = n16 * 16;
            uint32_t bk[4][4];
#pragma unroll
            for (int kt = 0; kt < 4; kt++) {
                const uint32_t bd = Ksu + ((nb + b_n) * AT_S + kt * 16 + b_ko) * 2;
                LDSM4(bk[kt][0], bk[kt][1], bk[kt][2], bk[kt][3], bd);
            }
            // term pairs (A,B): QhKh:(0,0)(1,1)  QlKh:(2,0)(3,1)  QhKl:(0,2)(1,3)
            const int pa[6] = {0, 1, 2, 3, 0, 1};
            const int pb[6] = {0, 1, 0, 1, 2, 3};
#pragma unroll
            for (int t = 0; t < 6; t++) {
                MMA16816(S[2 * n16],     aq[pa[t]], bk[pb[t]][0], bk[pb[t]][1]);
                MMA16816(S[2 * n16 + 1], aq[pa[t]], bk[pb[t]][2], bk[pb[t]][3]);
            }
        }

        // bias + mask (coalesced f2 loads), pad cols -> -1e9
        const int r0 = mb + (lane >> 2), r1 = r0 + 8;
        const int r0e = min(r0, 195), r1e = min(r1, 195);
#pragma unroll
        for (int nt = 0; nt < 26; nt++) {
            const int c = nt * 8 + ((lane & 3) << 1);
            const int ce = min(c, 194);
            const float2 b0v = *(const float2*)(bmB + r0e * NTOK + ce);
            const float2 b1v = *(const float2*)(bmB + r1e * NTOK + ce);
            const float2 m0 = *(const float2*)(mkB + (size_t)r0e * NTOK + ce);
            const float2 m1 = *(const float2*)(mkB + (size_t)r1e * NTOK + ce);
            S[nt][0] += b0v.x + m0.x; S[nt][1] += b0v.y + m0.y;
            S[nt][2] += b1v.x + m1.x; S[nt][3] += b1v.y + m1.y;
            if (c >= NTOK) { S[nt][0] = S[nt][1] = S[nt][2] = S[nt][3] = -1e9f; }
        }

        // softmax (rows r0: elems 0,1 ; rows r1: elems 2,3) — quad reduction
        float mx0 = -1e30f, mx1 = -1e30f;
#pragma unroll
        for (int nt = 0; nt < 26; nt++) {
            mx0 = fmaxf(mx0, fmaxf(S[nt][0], S[nt][1]));
            mx1 = fmaxf(mx1, fmaxf(S[nt][2], S[nt][3]));
        }
        mx0 = fmaxf(mx0, __shfl_xor_sync(0xffffffffu, mx0, 1));
        mx0 = fmaxf(mx0, __shfl_xor_sync(0xffffffffu, mx0, 2));
        mx1 = fmaxf(mx1, __shfl_xor_sync(0xffffffffu, mx1, 1));
        mx1 = fmaxf(mx1, __shfl_xor_sync(0xffffffffu, mx1, 2));
        float s0 = 0.f, s1 = 0.f;
#pragma unroll
        for (int nt = 0; nt < 26; nt++) {
            S[nt][0] = __expf(S[nt][0] - mx0); S[nt][1] = __expf(S[nt][1] - mx0);
            S[nt][2] = __expf(S[nt][2] - mx1); S[nt][3] = __expf(S[nt][3] - mx1);
            s0 += S[nt][0] + S[nt][1];
            s1 += S[nt][2] + S[nt][3];
        }
        s0 += __shfl_xor_sync(0xffffffffu, s0, 1);
        s0 += __shfl_xor_sync(0xffffffffu, s0, 2);
        s1 += __shfl_xor_sync(0xffffffffu, s1, 1);
        s1 += __shfl_xor_sync(0xffffffffu, s1, 2);
        const float inv0 = 1.0f / s0, inv1 = 1.0f / s1;

        // PV: O[m16 x d32]  (unnormalized P; normalize at store)
        float O[4][4];
#pragma unroll
        for (int j = 0; j < 4; j++)
#pragma unroll
            for (int e = 0; e < 4; e++) O[j][e] = 0.f;

#pragma unroll
        for (int kt = 0; kt < 13; kt++) {
            uint32_t ph[4], pl[4];
#pragma unroll
            for (int half = 0; half < 2; half++) {
                const float e0 = S[2 * kt + half][0], e1 = S[2 * kt + half][1];
                const float e2 = S[2 * kt + half][2], e3 = S[2 * kt + half][3];
                const uint32_t h01 = bfpack(e0, e1);
                const uint32_t h23 = bfpack(e2, e3);
                const float f0 = __uint_as_float(h01 << 16);
                const float f1 = __uint_as_float(h01 & 0xffff0000u);
                const float f2 = __uint_as_float(h23 << 16);
                const float f3 = __uint_as_float(h23 & 0xffff0000u);
                ph[half * 2 + 0] = h01;
                ph[half * 2 + 1] = h23;
                pl[half * 2 + 0] = bfpack(e0 - f0, e1 - f1);
                pl[half * 2 + 1] = bfpack(e2 - f2, e3 - f3);
            }
            uint32_t pa_h[4] = {ph[0], ph[1], ph[2], ph[3]};
            uint32_t pa_l[4] = {pl[0], pl[1], pl[2], pl[3]};

            uint32_t vh[2][4], vl[2][4];
#pragma unroll
            for (int g = 0; g < 2; g++) {
                const uint32_t vda =
                    Vsu + ((kt * 16 + (lane & 15)) * AT_S + g * 16 + ((lane >> 4) << 3)) * 2;
                LDSM4T(vh[g][0], vh[g][1], vh[g][2], vh[g][3], vda);
                const uint32_t vdl = vda + 32 * 2;
                LDSM4T(vl[g][0], vl[g][1], vl[g][2], vl[g][3], vdl);
            }
#pragma unroll
            for (int g = 0; g < 2; g++) {
                MMA16816(O[g * 2 + 0], pa_h, vh[g][0], vh[g][1]);
                MMA16816(O[g * 2 + 1], pa_h, vh[g][2], vh[g][3]);
                MMA16816(O[g * 2 + 0], pa_l, vh[g][0], vh[g][1]);
                MMA16816(O[g * 2 + 1], pa_l, vh[g][2], vh[g][3]);
                MMA16816(O[g * 2 + 0], pa_h, vl[g][0], vl[g][1]);
                MMA16816(O[g * 2 + 1], pa_h, vl[g][2], vl[g][3]);
            }
        }

        // store split-bf16 directly into g_ob (fused conv_act<1>)
        const int dcol = (lane & 3) << 1;
        if (r0 < NTOK) {
            __nv_bfloat16* op = g_ob + ((size_t)b * NTOK + r0) * KEXT + h * HDIM + dcol;
#pragma unroll
            for (int j = 0; j < 4; j++) {
                const float v0 = O[j][0] * inv0, v1 = O[j][1] * inv0;
                const uint32_t hi = bfpack(v0, v1);
                const float f0 = __uint_as_float(hi << 16);
                const float f1 = __uint_as_float(hi & 0xffff0000u);
                const uint32_t lo = bfpack(v0 - f0, v1 - f1);
                *(uint32_t*)(op + j * 8)       = hi;
                *(uint32_t*)(op + j * 8 + 256) = lo;
                *(uint32_t*)(op + j * 8 + 512) = hi;
            }
        }
        if (r1 < NTOK) {
            __nv_bfloat16* op = g_ob + ((size_t)b * NTOK + r1) * KEXT + h * HDIM + dcol;
#pragma unroll
            for (int j = 0; j < 4; j++) {
                const float v0 = O[j][2] * inv1, v1 = O[j][3] * inv1;
                const uint32_t hi = bfpack(v0, v1);
                const float f0 = __uint_as_float(hi << 16);
                const float f1 = __uint_as_float(hi & 0xffff0000u);
                const uint32_t lo = bfpack(v0 - f0, v1 - f1);
                *(uint32_t*)(op + j * 8)       = hi;
                *(uint32_t*)(op + j * 8 + 256) = lo;
                *(uint32_t*)(op + j * 8 + 512) = hi;
            }
        }
    }
}

// ---------------------------------------------------------------------------
extern "C" void kernel_launch(void* const* d_in, const int* in_sizes, int n_in,
                              void* d_out, int out_size)
{
    const float* x          = (const float*)d_in[0];
    const float* mask       = (const float*)d_in[1];
    const float* qkv_w      = (const float*)d_in[2];
    const float* qkv_b      = (const float*)d_in[3];
    const float* proj_w     = (const float*)d_in[4];
    const float* proj_b     = (const float*)d_in[5];
    const float* bias_table = (const float*)d_in[6];
    const int*   rel_index  = (const int*)d_in[7];
    float* out = (float*)d_out;

    cudaFuncSetAttribute(attn_mma,
                         cudaFuncAttributeMaxDynamicSharedMemorySize, ASMEM_BYTES);
    cudaFuncSetAttribute(hmma_gemm<0>,
                         cudaFuncAttributeMaxDynamicSharedMemorySize, GSMEM);
    cudaFuncSetAttribute(hmma_gemm<1>,
                         cudaFuncAttributeMaxDynamicSharedMemorySize, GSMEM);

    __nv_bfloat16 *xb, *wq, *wp;
    cudaGetSymbolAddress((void**)&xb, g_xb);
    cudaGetSymbolAddress((void**)&wq, g_wq);
    cudaGetSymbolAddress((void**)&wp, g_wp);

    // 1) split-bf16 conversions + bias gather precompute
    conv_act<<<MROWS * 64 / 256, 256>>>(x, xb);
    conv_wgt<<<768 * 64 / 256, 256>>>(qkv_w, wq);
    conv_wgt<<<256 * 64 / 256, 256>>>(proj_w, wp);
    bias_pre<<<(NTOK * NTOK + 255) / 256, 256>>>(bias_table, rel_index);
    // 2) QKV projection (HMMA): N tiles 0..5 -> q (scaled), k, v
    hmma_gemm<0><<<dim3(6, MROWS / 128), 256, GSMEM>>>(qkv_b, nullptr);
    // 3) HMMA flash attention -> g_ob (split bf16, fused)
    attn_mma<<<B__ * NH, 128, ASMEM_BYTES>>>(mask);
    // 4) output projection (HMMA)
    hmma_gemm<1><<<dim3(2, MROWS / 128), 256, GSMEM>>>(proj_b, out);
}

// round 13
// speedup vs baseline: 1.5602x; 1.0162x over previous
#include <cuda_runtime.h>
#include <cuda_bf16.h>
#include <cstdint>

#define B__   256
#define NTOK  196
#define CDIM  256
#define NH    8
#define HDIM  32
#define MROWS (B__ * NTOK)          // 50176 = 392*128
#define KEXT  768                   // 3*256 split-bf16 K
#define QSCALE 0.17677669529663687f // 1/sqrt(32)

typedef unsigned long long ull;

// ---------------- scratch (device globals) ----------------
__device__ float g_q[MROWS * CDIM];
__device__ float g_k[MROWS * CDIM];
__device__ float g_v[MROWS * CDIM];
__device__ float g_bm[NH * NTOK * NTOK];             // bias gathered per head
__device__ __nv_bfloat16 g_xb[(size_t)MROWS * KEXT]; // x split  [Ah, Al, Ah]
__device__ __nv_bfloat16 g_ob[(size_t)MROWS * KEXT]; // attn-out split
__device__ __nv_bfloat16 g_wq[768 * KEXT];           // qkv_w split [Bh, Bh, Bl]
__device__ __nv_bfloat16 g_wp[256 * KEXT];           // proj_w split

// ---------------- small PTX helpers ----------------
__device__ __forceinline__ uint32_t s2u(const void* p) {
    return (uint32_t)__cvta_generic_to_shared(p);
}
#define CP16(dst, src) \
    asm volatile("cp.async.ca.shared.global [%0], [%1], 16;" :: "r"(dst), "l"(src))
#define CP_COMMIT() asm volatile("cp.async.commit_group;" ::: "memory")
#define CP_WAIT(n)  asm volatile("cp.async.wait_group %0;" :: "n"(n) : "memory")

#define LDSM4(r0, r1, r2, r3, addr) \
    asm volatile("ldmatrix.sync.aligned.m8n8.x4.shared.b16 {%0,%1,%2,%3}, [%4];" \
                 : "=r"(r0), "=r"(r1), "=r"(r2), "=r"(r3) : "r"(addr))
#define LDSM4T(r0, r1, r2, r3, addr) \
    asm volatile("ldmatrix.sync.aligned.m8n8.x4.trans.shared.b16 {%0,%1,%2,%3}, [%4];" \
                 : "=r"(r0), "=r"(r1), "=r"(r2), "=r"(r3) : "r"(addr))

#define MMA16816(d, a, b0, b1) \
    asm volatile("mma.sync.aligned.m16n8k16.row.col.f32.bf16.bf16.f32 " \
                 "{%0,%1,%2,%3}, {%4,%5,%6,%7}, {%8,%9}, {%0,%1,%2,%3};" \
                 : "+f"((d)[0]), "+f"((d)[1]), "+f"((d)[2]), "+f"((d)[3]) \
                 : "r"((a)[0]), "r"((a)[1]), "r"((a)[2]), "r"((a)[3]), \
                   "r"(b0), "r"(b1))

// pack two f32 into bf16x2: first arg -> low half
__device__ __forceinline__ uint32_t bfpack(float lo, float hi) {
    uint32_t r;
    asm("cvt.rn.bf16x2.f32 %0, %1, %2;" : "=r"(r) : "f"(hi), "f"(lo));
    return r;
}
// split float2 into (hi, lo) bf16x2 pair (lo = residual)
__device__ __forceinline__ void split2(float2 v, uint32_t& hi, uint32_t& lo) {
    hi = bfpack(v.x, v.y);
    const float f0 = __uint_as_float(hi << 16);
    const float f1 = __uint_as_float(hi & 0xffff0000u);
    lo = bfpack(v.x - f0, v.y - f1);
}

// ---------------- split-bf16 conversion ----------------
__device__ __forceinline__ uint32_t pk2(float x, float y) {
    __nv_bfloat162 t = __float22bfloat162_rn(make_float2(x, y));
    return *(uint32_t*)&t;
}
// activations: [M][256] f32 -> [M][768] bf16 as {hi, lo, hi}
__global__ __launch_bounds__(256) void conv_act(const float* __restrict__ src,
                                                __nv_bfloat16* __restrict__ dst) {
    int i = blockIdx.x * 256 + threadIdx.x;       // float4 index, total MROWS*64
    float4 v = ((const float4*)src)[i];
    int row = i >> 6, c = (i & 63) << 2;
    __nv_bfloat16 hx = __float2bfloat16(v.x), hy = __float2bfloat16(v.y);
    __nv_bfloat16 hz = __float2bfloat16(v.z), hw = __float2bfloat16(v.w);
    float lx = v.x - __bfloat162float(hx), ly = v.y - __bfloat162float(hy);
    float lz = v.z - __bfloat162float(hz), lw = v.w - __bfloat162float(hw);
    uint2 hi; hi.x = pk2(__bfloat162float(hx), __bfloat162float(hy));
              hi.y = pk2(__bfloat162float(hz), __bfloat162float(hw));
    uint2 lo; lo.x = pk2(lx, ly); lo.y = pk2(lz, lw);
    __nv_bfloat16* base = dst + (size_t)row * KEXT + c;
    *(uint2*)(base)       = hi;
    *(uint2*)(base + 256) = lo;
    *(uint2*)(base + 512) = hi;
}
// weights: [N][256] f32 -> [N][768] bf16 as {hi, hi, lo}
__global__ __launch_bounds__(256) void conv_wgt(const float* __restrict__ src,
                                                __nv_bfloat16* __restrict__ dst) {
    int i = blockIdx.x * 256 + threadIdx.x;
    float4 v = ((const float4*)src)[i];
    int row = i >> 6, c = (i & 63) << 2;
    __nv_bfloat16 hx = __float2bfloat16(v.x), hy = __float2bfloat16(v.y);
    __nv_bfloat16 hz = __float2bfloat16(v.z), hw = __float2bfloat16(v.w);
    float lx = v.x - __bfloat162float(hx), ly = v.y - __bfloat162float(hy);
    float lz = v.z - __bfloat162float(hz), lw = v.w - __bfloat162float(hw);
    uint2 hi; hi.x = pk2(__bfloat162float(hx), __bfloat162float(hy));
              hi.y = pk2(__bfloat162float(hz), __bfloat162float(hw));
    uint2 lo; lo.x = pk2(lx, ly); lo.y = pk2(lz, lw);
    __nv_bfloat16* base = dst + (size_t)row * KEXT + c;
    *(uint2*)(base)       = hi;
    *(uint2*)(base + 256) = hi;
    *(uint2*)(base + 512) = lo;
}

// bias gather precompute: g_bm[h][n][m] = bias_table[rel_index[n*196+m]][h]
__global__ __launch_bounds__(256) void bias_pre(const float* __restrict__ bt,
                                                const int* __restrict__ ri) {
    int i = blockIdx.x * 256 + threadIdx.x;
    if (i < NTOK * NTOK) {
        const int idx = ri[i];
#pragma unroll
        for (int h = 0; h < NH; h++)
            g_bm[h * (NTOK * NTOK) + i] = bt[idx * NH + h];
    }
}

// ---------------- HMMA bf16 GEMM (unchanged from R7) ----------------
#define BK     32
#define LDS_S  40
#define NSTG   (KEXT / BK)          // 24
#define STAGEF (128 * LDS_S)
#define GSMEM  (4 * STAGEF * 2 * 2) // 81920 bytes

template <int MODE>
__global__ __launch_bounds__(256, 2) void hmma_gemm(const float* __restrict__ bias,
                                                    float* __restrict__ out) {
    extern __shared__ __align__(16) __nv_bfloat16 smb[];
    __nv_bfloat16* As = smb;
    __nv_bfloat16* Bs = smb + 4 * STAGEF;

    const int tid = threadIdx.x, lane = tid & 31, wid = tid >> 5;
    const int nt = blockIdx.x;
    const int rowBase = blockIdx.y << 7;
    const int colBase = nt << 7;

    const __nv_bfloat16* Ag = ((MODE == 0) ? g_xb : g_ob) + (size_t)rowBase * KEXT;
    const __nv_bfloat16* Bg = ((MODE == 0) ? g_wq : g_wp) + (size_t)colBase * KEXT;

    const int c0r = tid >> 2, c0c = (tid & 3) << 3;
    const int c1r = (tid + 256) >> 2, c1c = c0c;

#define LOADSTAGE(s) do { \
    const int kt = (s) * BK; \
    __nv_bfloat16* ap = As + ((s) & 3) * STAGEF; \
    __nv_bfloat16* bp = Bs + ((s) & 3) * STAGEF; \
    CP16(s2u(ap + c0r * LDS_S + c0c), Ag + (size_t)c0r * KEXT + kt + c0c); \
    CP16(s2u(ap + c1r * LDS_S + c1c), Ag + (size_t)c1r * KEXT + kt + c1c); \
    CP16(s2u(bp + c0r * LDS_S + c0c), Bg + (size_t)c0r * KEXT + kt + c0c); \
    CP16(s2u(bp + c1r * LDS_S + c1c), Bg + (size_t)c1r * KEXT + kt + c1c); \
    CP_COMMIT(); \
} while (0)

    const int wm = wid & 1, wn = wid >> 1;
    const int Am = wm * 64, Bn = wn * 32;
    const int a_row = lane & 15;
    const int a_ko  = (lane >> 4) << 3;
    const int b_n   = ((lane >> 4) << 3) + (lane & 7);
    const int b_ko  = ((lane >> 3) & 1) << 3;

    float d[4][4][4];
#pragma unroll
    for (int i = 0; i < 4; i++)
#pragma unroll
        for (int j = 0; j < 4; j++)
#pragma unroll
            for (int e = 0; e < 4; e++) d[i][j][e] = 0.f;

    LOADSTAGE(0);
    LOADSTAGE(1);
    LOADSTAGE(2);

    for (int s = 0; s < NSTG; s++) {
        if (s < NSTG - 2)       CP_WAIT(2);
        else if (s == NSTG - 2) CP_WAIT(1);
        else                    CP_WAIT(0);
        __syncthreads();

        const __nv_bfloat16* abuf = As + (s & 3) * STAGEF;
        const __nv_bfloat16* bbuf = Bs + (s & 3) * STAGEF;
#pragma unroll
        for (int kk = 0; kk < BK; kk += 16) {
            uint32_t a[4][4];
#pragma unroll
            for (int mi = 0; mi < 4; mi++) {
                const uint32_t ad =
                    s2u(abuf + (Am + mi * 16 + a_row) * LDS_S + kk + a_ko);
                LDSM4(a[mi][0], a[mi][1], a[mi][2], a[mi][3], ad);
            }
            uint32_t b[2][4];
#pragma unroll
            for (int nb = 0; nb < 2; nb++) {
                const uint32_t bd =
                    s2u(bbuf + (Bn + nb * 16 + b_n) * LDS_S + kk + b_ko);
                LDSM4(b[nb][0], b[nb][1], b[nb][2], b[nb][3], bd);
            }
#pragma unroll
            for (int mi = 0; mi < 4; mi++)
#pragma unroll
                for (int nj = 0; nj < 4; nj++)
                    MMA16816(d[mi][nj], a[mi], b[nj >> 1][(nj & 1) * 2],
                             b[nj >> 1][(nj & 1) * 2 + 1]);
        }
        if (s + 3 < NSTG) LOADSTAGE(s + 3);
    }
#undef LOADSTAGE

    const int erow = lane >> 2;
    const int ecol = (lane & 3) << 1;
#pragma unroll
    for (int mi = 0; mi < 4; mi++) {
#pragma unroll
        for (int nj = 0; nj < 4; nj++) {
            const int col = colBase + Bn + nj * 8 + ecol;
            const float b0 = bias[col], b1 = bias[col + 1];
#pragma unroll
            for (int half = 0; half < 2; half++) {
                const int r = rowBase + Am + mi * 16 + erow + half * 8;
                float2 v;
                v.x = d[mi][nj][half * 2 + 0] + b0;
                v.y = d[mi][nj][half * 2 + 1] + b1;
                if (MODE == 0) {
                    const int sel = col >> 8, h = (col >> 5) & 7, dd = col & 31;
                    const int bb = r / NTOK, nn = r - bb * NTOK;
                    float* dst = (sel == 0) ? g_q : (sel == 1) ? g_k : g_v;
                    if (sel == 0) { v.x *= QSCALE; v.y *= QSCALE; }
                    *(float2*)&dst[(((size_t)bb * NH + h) * NTOK + nn) * HDIM + dd] = v;
                } else {
                    *(float2*)&out[(size_t)r * CDIM + col] = v;
                }
            }
        }
    }
}

// ---------------- HMMA flash attention ----------------
// CTA = one (b,h); 4 warps; M padded 196->208; K/V (hi|lo) in SMEM, Q
// fragments built directly from gmem (no Qs) -> 58.5KB smem -> 3 CTAs/SM.
#define AT_S   72                          // smem row stride (bf16), conflict-free
#define AROWS  208
#define ASMEM_BYTES (2 * AROWS * AT_S * 2)  // 59904

__global__ __launch_bounds__(128, 3) void attn_mma(
    const float* __restrict__ mask)
{
    extern __shared__ __align__(16) __nv_bfloat16 smb[];
    __nv_bfloat16* Ks = smb;
    __nv_bfloat16* Vs = smb + AROWS * AT_S;

    const int tid = threadIdx.x, lane = tid & 31, wid = tid >> 5;
    const int bh = blockIdx.x, b = bh >> 3, h = bh & 7;
    const size_t base = (size_t)bh * (NTOK * HDIM);

    // zero pad rows 196..207 (cols 0..63 used by ldmatrix)
    for (int i = tid; i < 12 * 64; i += 128) {
        const int r = 196 + (i >> 6), c = i & 63;
        const __nv_bfloat16 z = __float2bfloat16(0.f);
        Ks[r * AT_S + c] = z; Vs[r * AT_S + c] = z;
    }
    // load + split k/v
    for (int i = tid; i < NTOK * HDIM; i += 128) {
        const int r = i >> 5, d = i & 31;
        const float k = g_k[base + i], v = g_v[base + i];
        const __nv_bfloat16 kh = __float2bfloat16(k);
        const __nv_bfloat16 vh = __float2bfloat16(v);
        Ks[r * AT_S + d] = kh; Ks[r * AT_S + 32 + d] = __float2bfloat16(k - __bfloat162float(kh));
        Vs[r * AT_S + d] = vh; Vs[r * AT_S + 32 + d] = __float2bfloat16(v - __bfloat162float(vh));
    }
    __syncthreads();

    const uint32_t Ksu = s2u(Ks), Vsu = s2u(Vs);
    const float* bmB = g_bm + h * (NTOK * NTOK);
    const float* mkB = mask + (size_t)(b & 63) * (NTOK * NTOK);

    const int b_n   = ((lane >> 4) << 3) + (lane & 7);
    const int b_ko  = ((lane >> 3) & 1) << 3;

    for (int mt = wid; mt < 13; mt += 4) {
        const int mb = mt * 16;

        // Q A-fragments built directly from g_q (canonical m16k16 layout):
        // reg0=(rq0, c..c+1), reg1=(rq1, ..), reg2=(rq0, c+8..9), reg3=(rq1, ..)
        // aq[0..1] = hi (d 0-15 / 16-31), aq[2..3] = lo residuals
        uint32_t aq[4][4];
        {
            const int rq0 = min(mb + (lane >> 2), 195);
            const int rq1 = min(mb + (lane >> 2) + 8, 195);
            const int cq = (lane & 3) << 1;
            const float* qp0 = g_q + base + rq0 * HDIM + cq;
            const float* qp1 = g_q + base + rq1 * HDIM + cq;
#pragma unroll
            for (int g = 0; g < 2; g++) {
                split2(*(const float2*)(qp0 + g * 16),     aq[g][0], aq[g + 2][0]);
                split2(*(const float2*)(qp1 + g * 16),     aq[g][1], aq[g + 2][1]);
                split2(*(const float2*)(qp0 + g * 16 + 8), aq[g][2], aq[g + 2][2]);
                split2(*(const float2*)(qp1 + g * 16 + 8), aq[g][3], aq[g + 2][3]);
            }
        }

        float S[26][4];
#pragma unroll
        for (int nt = 0; nt < 26; nt++)
#pragma unroll
            for (int e = 0; e < 4; e++) S[nt][e] = 0.f;

        // QK^T
#pragma unroll
        for (int n16 = 0; n16 < 13; n16++) {
            const int nb = n16 * 16;
            uint32_t bk[4][4];
#pragma unroll
            for (int kt = 0; kt < 4; kt++) {
                const uint32_t bd = Ksu + ((nb + b_n) * AT_S + kt * 16 + b_ko) * 2;
                LDSM4(bk[kt][0], bk[kt][1], bk[kt][2], bk[kt][3], bd);
            }
            // term pairs (A,B): QhKh:(0,0)(1,1)  QlKh:(2,0)(3,1)  QhKl:(0,2)(1,3)
            const int pa[6] = {0, 1, 2, 3, 0, 1};
            const int pb[6] = {0, 1, 0, 1, 2, 3};
#pragma unroll
            for (int t = 0; t < 6; t++) {
                MMA16816(S[2 * n16],     aq[pa[t]], bk[pb[t]][0], bk[pb[t]][1]);
                MMA16816(S[2 * n16 + 1], aq[pa[t]], bk[pb[t]][2], bk[pb[t]][3]);
            }
        }

        // bias + mask (coalesced f2 loads), pad cols -> -1e9
        const int r0 = mb + (lane >> 2), r1 = r0 + 8;
        const int r0e = min(r0, 195), r1e = min(r1, 195);
#pragma unroll
        for (int nt = 0; nt < 26; nt++) {
            const int c = nt * 8 + ((lane & 3) << 1);
            const int ce = min(c, 194);
            const float2 b0v = *(const float2*)(bmB + r0e * NTOK + ce);
            const float2 b1v = *(const float2*)(bmB + r1e * NTOK + ce);
            const float2 m0 = *(const float2*)(mkB + (size_t)r0e * NTOK + ce);
            const float2 m1 = *(const float2*)(mkB + (size_t)r1e * NTOK + ce);
            S[nt][0] += b0v.x + m0.x; S[nt][1] += b0v.y + m0.y;
            S[nt][2] += b1v.x + m1.x; S[nt][3] += b1v.y + m1.y;
            if (c >= NTOK) { S[nt][0] = S[nt][1] = S[nt][2] = S[nt][3] = -1e9f; }
        }

        // softmax (rows r0: elems 0,1 ; rows r1: elems 2,3) — quad reduction
        float mx0 = -1e30f, mx1 = -1e30f;
#pragma unroll
        for (int nt = 0; nt < 26; nt++) {
            mx0 = fmaxf(mx0, fmaxf(S[nt][0], S[nt][1]));
            mx1 = fmaxf(mx1, fmaxf(S[nt][2], S[nt][3]));
        }
        mx0 = fmaxf(mx0, __shfl_xor_sync(0xffffffffu, mx0, 1));
        mx0 = fmaxf(mx0, __shfl_xor_sync(0xffffffffu, mx0, 2));
        mx1 = fmaxf(mx1, __shfl_xor_sync(0xffffffffu, mx1, 1));
        mx1 = fmaxf(mx1, __shfl_xor_sync(0xffffffffu, mx1, 2));
        float s0 = 0.f, s1 = 0.f;
#pragma unroll
        for (int nt = 0; nt < 26; nt++) {
            S[nt][0] = __expf(S[nt][0] - mx0); S[nt][1] = __expf(S[nt][1] - mx0);
            S[nt][2] = __expf(S[nt][2] - mx1); S[nt][3] = __expf(S[nt][3] - mx1);
            s0 += S[nt][0] + S[nt][1];
            s1 += S[nt][2] + S[nt][3];
        }
        s0 += __shfl_xor_sync(0xffffffffu, s0, 1);
        s0 += __shfl_xor_sync(0xffffffffu, s0, 2);
        s1 += __shfl_xor_sync(0xffffffffu, s1, 1);
        s1 += __shfl_xor_sync(0xffffffffu, s1, 2);
        const float inv0 = 1.0f / s0, inv1 = 1.0f / s1;

        // PV: O[m16 x d32]  (unnormalized P; normalize at store)
        float O[4][4];
#pragma unroll
        for (int j = 0; j < 4; j++)
#pragma unroll
            for (int e = 0; e < 4; e++) O[j][e] = 0.f;

#pragma unroll
        for (int kt = 0; kt < 13; kt++) {
            uint32_t ph[4], pl[4];
#pragma unroll
            for (int half = 0; half < 2; half++) {
                const float e0 = S[2 * kt + half][0], e1 = S[2 * kt + half][1];
                const float e2 = S[2 * kt + half][2], e3 = S[2 * kt + half][3];
                const uint32_t h01 = bfpack(e0, e1);
                const uint32_t h23 = bfpack(e2, e3);
                const float f0 = __uint_as_float(h01 << 16);
                const float f1 = __uint_as_float(h01 & 0xffff0000u);
                const float f2 = __uint_as_float(h23 << 16);
                const float f3 = __uint_as_float(h23 & 0xffff0000u);
                ph[half * 2 + 0] = h01;
                ph[half * 2 + 1] = h23;
                pl[half * 2 + 0] = bfpack(e0 - f0, e1 - f1);
                pl[half * 2 + 1] = bfpack(e2 - f2, e3 - f3);
            }
            uint32_t pa_h[4] = {ph[0], ph[1], ph[2], ph[3]};
            uint32_t pa_l[4] = {pl[0], pl[1], pl[2], pl[3]};

            uint32_t vh[2][4], vl[2][4];
#pragma unroll
            for (int g = 0; g < 2; g++) {
                const uint32_t vda =
                    Vsu + ((kt * 16 + (lane & 15)) * AT_S + g * 16 + ((lane >> 4) << 3)) * 2;
                LDSM4T(vh[g][0], vh[g][1], vh[g][2], vh[g][3], vda);
                const uint32_t vdl = vda + 32 * 2;
                LDSM4T(vl[g][0], vl[g][1], vl[g][2], vl[g][3], vdl);
            }
#pragma unroll
            for (int g = 0; g < 2; g++) {
                MMA16816(O[g * 2 + 0], pa_h, vh[g][0], vh[g][1]);
                MMA16816(O[g * 2 + 1], pa_h, vh[g][2], vh[g][3]);
                MMA16816(O[g * 2 + 0], pa_l, vh[g][0], vh[g][1]);
                MMA16816(O[g * 2 + 1], pa_l, vh[g][2], vh[g][3]);
                MMA16816(O[g * 2 + 0], pa_h, vl[g][0], vl[g][1]);
                MMA16816(O[g * 2 + 1], pa_h, vl[g][2], vl[g][3]);
            }
        }

        // store split-bf16 directly into g_ob (fused conversion)
        const int dcol = (lane & 3) << 1;
        if (r0 < NTOK) {
            __nv_bfloat16* op = g_ob + ((size_t)b * NTOK + r0) * KEXT + h * HDIM + dcol;
#pragma unroll
            for (int j = 0; j < 4; j++) {
                const float v0 = O[j][0] * inv0, v1 = O[j][1] * inv0;
                uint32_t hi, lo;
                split2(make_float2(v0, v1), hi, lo);
                *(uint32_t*)(op + j * 8)       = hi;
                *(uint32_t*)(op + j * 8 + 256) = lo;
                *(uint32_t*)(op + j * 8 + 512) = hi;
            }
        }
        if (r1 < NTOK) {
            __nv_bfloat16* op = g_ob + ((size_t)b * NTOK + r1) * KEXT + h * HDIM + dcol;
#pragma unroll
            for (int j = 0; j < 4; j++) {
                const float v0 = O[j][2] * inv1, v1 = O[j][3] * inv1;
                uint32_t hi, lo;
                split2(make_float2(v0, v1), hi, lo);
                *(uint32_t*)(op + j * 8)       = hi;
                *(uint32_t*)(op + j * 8 + 256) = lo;
                *(uint32_t*)(op + j * 8 + 512) = hi;
            }
        }
    }
}

// ---------------------------------------------------------------------------
extern "C" void kernel_launch(void* const* d_in, const int* in_sizes, int n_in,
                              void* d_out, int out_size)
{
    const float* x          = (const float*)d_in[0];
    const float* mask       = (const float*)d_in[1];
    const float* qkv_w      = (const float*)d_in[2];
    const float* qkv_b      = (const float*)d_in[3];
    const float* proj_w     = (const float*)d_in[4];
    const float* proj_b     = (const float*)d_in[5];
    const float* bias_table = (const float*)d_in[6];
    const int*   rel_index  = (const int*)d_in[7];
    float* out = (float*)d_out;

    cudaFuncSetAttribute(attn_mma,
                         cudaFuncAttributeMaxDynamicSharedMemorySize, ASMEM_BYTES);
    cudaFuncSetAttribute(hmma_gemm<0>,
                         cudaFuncAttributeMaxDynamicSharedMemorySize, GSMEM);
    cudaFuncSetAttribute(hmma_gemm<1>,
                         cudaFuncAttributeMaxDynamicSharedMemorySize, GSMEM);

    __nv_bfloat16 *xb, *wq, *wp;
    cudaGetSymbolAddress((void**)&xb, g_xb);
    cudaGetSymbolAddress((void**)&wq, g_wq);
    cudaGetSymbolAddress((void**)&wp, g_wp);

    // 1) split-bf16 conversions + bias gather precompute
    conv_act<<<MROWS * 64 / 256, 256>>>(x, xb);
    conv_wgt<<<768 * 64 / 256, 256>>>(qkv_w, wq);
    conv_wgt<<<256 * 64 / 256, 256>>>(proj_w, wp);
    bias_pre<<<(NTOK * NTOK + 255) / 256, 256>>>(bias_table, rel_index);
    // 2) QKV projection (HMMA): N tiles 0..5 -> q (scaled), k, v
    hmma_gemm<0><<<dim3(6, MROWS / 128), 256, GSMEM>>>(qkv_b, nullptr);
    // 3) HMMA flash attention -> g_ob (split bf16, fused)
    attn_mma<<<B__ * NH, 128, ASMEM_BYTES>>>(mask);
    // 4) output projection (HMMA)
    hmma_gemm<1><<<dim3(2, MROWS / 128), 256, GSMEM>>>(proj_b, out);
}